// round 3
// baseline (speedup 1.0000x reference)
#include <cuda_runtime.h>

// Problem constants
#define BDIM   64
#define CIN    256
#define COUT   256
#define CS     256
#define HIDDEN 64
#define KEXP   4
#define LDIM   1024
#define TEMPR  30.0f

// Conv tiling
#define OTILE  32
#define ICCH   16
#define LCH    256

// Routing weights (softmax attention per sample), computed by att_kernel
__device__ float g_att[BDIM * KEXP];

// ---------------------------------------------------------------------------
// Kernel 1: routing MLP + softmax.  One block per sample, 64 threads.
//   h = relu(w1 @ cond_b)   (HIDDEN=64 dots of CS=256)
//   logits = w2 @ h         (K=4 dots of 64)
//   att = softmax(logits / TEMP)
// ---------------------------------------------------------------------------
__global__ void att_kernel(const float* __restrict__ cond,
                           const float* __restrict__ w1,
                           const float* __restrict__ w2) {
    int b = blockIdx.x;
    int j = threadIdx.x;  // 0..63
    __shared__ float h[HIDDEN];
    __shared__ float logits[KEXP];

    const float* cb  = cond + b * CS;
    const float* w1j = w1 + j * CS;
    float acc = 0.f;
    #pragma unroll 8
    for (int c = 0; c < CS; c++) acc = fmaf(w1j[c], cb[c], acc);
    h[j] = fmaxf(acc, 0.f);
    __syncthreads();

    if (j < KEXP) {
        const float* w2j = w2 + j * HIDDEN;
        float s = 0.f;
        #pragma unroll 8
        for (int c = 0; c < HIDDEN; c++) s = fmaf(w2j[c], h[c], s);
        logits[j] = s / TEMPR;
    }
    __syncthreads();

    if (j == 0) {
        float m = logits[0];
        #pragma unroll
        for (int k = 1; k < KEXP; k++) m = fmaxf(m, logits[k]);
        float e[KEXP];
        float ssum = 0.f;
        #pragma unroll
        for (int k = 0; k < KEXP; k++) { e[k] = expf(logits[k] - m); ssum += e[k]; }
        float inv = 1.f / ssum;
        #pragma unroll
        for (int k = 0; k < KEXP; k++) g_att[b * KEXP + k] = e[k] * inv;
    }
}

// ---------------------------------------------------------------------------
// Kernel 2: per-sample dynamic 1-D 3-tap conv (the 3x3 conv on (L,1) input
// reduces to the middle kernel column; side columns hit zero padding).
//
// Block = (sample b, 32 output channels).  256 threads:
//   warp = one group of 4 output channels (weight LDS are broadcasts)
//   lane = L position, each thread owns 8 L positions strided by 32
//          (conflict-free x LDS, coalesced output stores)
// Expert aggregation (sum over 4 experts weighted by att) is done on the fly
// while filling the weight tile in shared memory — the 9.4 MB weight tensor
// stays L2-resident across the 512 blocks.
// ---------------------------------------------------------------------------
__global__ __launch_bounds__(256, 2)
void conv_kernel(const float* __restrict__ x,
                 const float* __restrict__ weight,
                 const float* __restrict__ bias,
                 float* __restrict__ out) {
    __shared__ float xs[ICCH][LCH + 2];
    __shared__ float ws[ICCH][OTILE][3];

    const int b   = blockIdx.y;
    const int o0  = blockIdx.x * OTILE;
    const int tid = threadIdx.x;
    const int lg  = tid & 31;        // lane -> L offset
    const int ol  = (tid >> 5) * 4;  // warp -> output-channel group base

    const float a0 = g_att[b * 4 + 0];
    const float a1 = g_att[b * 4 + 1];
    const float a2 = g_att[b * 4 + 2];
    const float a3 = g_att[b * 4 + 3];

    // Aggregated bias for this thread's 4 output channels
    float bb[4];
    #pragma unroll
    for (int oo = 0; oo < 4; oo++) {
        int o = o0 + ol + oo;
        bb[oo] = a0 * bias[0 * COUT + o] + a1 * bias[1 * COUT + o]
               + a2 * bias[2 * COUT + o] + a3 * bias[3 * COUT + o];
    }

    const long estride = (long)COUT * CIN * 9;  // expert stride in weight tensor

    for (int l0 = 0; l0 < LDIM; l0 += LCH) {
        float acc[4][8];
        #pragma unroll
        for (int oo = 0; oo < 4; oo++)
            #pragma unroll
            for (int j = 0; j < 8; j++) acc[oo][j] = 0.f;

        for (int i0 = 0; i0 < CIN; i0 += ICCH) {
            __syncthreads();  // previous tile fully consumed

            // Fill aggregated weight tile: ws[r][o][t] = sum_k att_k * W[k][o0+o][i0+r][t][1]
            for (int e = tid; e < ICCH * OTILE * 3; e += 256) {
                int r   = e / (OTILE * 3);
                int rem = e % (OTILE * 3);
                int o   = rem / 3;
                int t   = rem % 3;
                long base = ((long)(o0 + o) * CIN + (i0 + r)) * 9 + t * 3 + 1;
                float v = a0 * __ldg(weight + base)
                        + a1 * __ldg(weight + base + estride)
                        + a2 * __ldg(weight + base + 2 * estride)
                        + a3 * __ldg(weight + base + 3 * estride);
                ws[r][o][t] = v;
            }

            // Stage x tile with halo: xs[r][c] = x[b][i0+r][l0 + c - 1]
            for (int e = tid; e < ICCH * (LCH + 2); e += 256) {
                int r  = e / (LCH + 2);
                int c  = e % (LCH + 2);
                int gl = l0 + c - 1;
                float v = 0.f;
                if (gl >= 0 && gl < LDIM)
                    v = x[((long)(b * CIN + i0 + r)) * LDIM + gl];
                xs[r][c] = v;
            }
            __syncthreads();

            #pragma unroll
            for (int r = 0; r < ICCH; r++) {
                float w[4][3];
                #pragma unroll
                for (int oo = 0; oo < 4; oo++) {
                    w[oo][0] = ws[r][ol + oo][0];
                    w[oo][1] = ws[r][ol + oo][1];
                    w[oo][2] = ws[r][ol + oo][2];
                }
                #pragma unroll
                for (int j = 0; j < 8; j++) {
                    int ll = lg + 32 * j;
                    float x0 = xs[r][ll];
                    float x1 = xs[r][ll + 1];
                    float x2 = xs[r][ll + 2];
                    #pragma unroll
                    for (int oo = 0; oo < 4; oo++) {
                        acc[oo][j] = fmaf(w[oo][0], x0, acc[oo][j]);
                        acc[oo][j] = fmaf(w[oo][1], x1, acc[oo][j]);
                        acc[oo][j] = fmaf(w[oo][2], x2, acc[oo][j]);
                    }
                }
            }
        }

        // Write this L chunk (coalesced: lanes consecutive in l)
        #pragma unroll
        for (int oo = 0; oo < 4; oo++) {
            float* op = out + ((long)(b * COUT + o0 + ol + oo)) * LDIM + l0;
            #pragma unroll
            for (int j = 0; j < 8; j++)
                op[lg + 32 * j] = acc[oo][j] + bb[oo];
        }
    }
}

// ---------------------------------------------------------------------------
extern "C" void kernel_launch(void* const* d_in, const int* in_sizes, int n_in,
                              void* d_out, int out_size) {
    const float* x      = (const float*)d_in[0];  // (64,256,1024,1)
    const float* cond   = (const float*)d_in[1];  // (64,256)
    const float* w1     = (const float*)d_in[2];  // (64,256)
    const float* w2     = (const float*)d_in[3];  // (4,64)
    const float* weight = (const float*)d_in[4];  // (4,256,256,3,3)
    const float* bias   = (const float*)d_in[5];  // (4,256)
    float* out = (float*)d_out;                   // (64,256,1024,1)

    att_kernel<<<BDIM, HIDDEN>>>(cond, w1, w2);
    dim3 grid(COUT / OTILE, BDIM);
    conv_kernel<<<grid, 256>>>(x, weight, bias, out);
}

// round 7
// speedup vs baseline: 4.2445x; 4.2445x over previous
#include <cuda_runtime.h>
#include <cuda_bf16.h>
#include <cstdint>

// ---------------- problem constants ----------------
#define NB     64
#define CINC   256
#define COUTC  256
#define CSC    256
#define HIDC   64
#define LDIMC  1024
#define TEMPR  30.0f

// ---------------- GEMM tiling ----------------
#define BM   128          // o per block
#define BN   128          // l per block
#define IC   32           // input channels per chunk
#define NCH  8            // CINC / IC

// ---------------- smem map (dynamic) ----------------
// [0,512)        : aggregated bias (128 floats)
// [512, +6*10240): A tiles, (tap,hi/lo), each 128 rows x 80B (64B data + pad)
// [61952, +10400): X hi tile, 130 rows x 80B
// [72352, +10400): X lo tile
#define OFF_A   512
#define ATS     10240
#define OFF_XH  61952
#define OFF_XL  72352
#define SMEMSZ  82752

// ---------------- device scratch ----------------
__device__ float g_att[NB * 4];
// aggregated weights, layout [b][tap][o][i], bf16 hi + bf16 residual
__device__ __align__(16) __nv_bfloat16 g_wh[(size_t)NB * 3 * COUTC * CINC];
__device__ __align__(16) __nv_bfloat16 g_wl[(size_t)NB * 3 * COUTC * CINC];

// ---------------- helpers ----------------
__device__ __forceinline__ uint32_t smem_u32(const void* p) {
    uint32_t a;
    asm("{ .reg .u64 t; cvta.to.shared.u64 t, %1; cvt.u32.u64 %0, t; }" : "=r"(a) : "l"(p));
    return a;
}
__device__ __forceinline__ void ldsm4(uint32_t (&r)[4], uint32_t addr) {
    asm volatile("ldmatrix.sync.aligned.m8n8.x4.shared.b16 {%0,%1,%2,%3}, [%4];"
                 : "=r"(r[0]), "=r"(r[1]), "=r"(r[2]), "=r"(r[3]) : "r"(addr));
}
__device__ __forceinline__ void mma16816(float (&d)[4], const uint32_t (&a)[4],
                                         const uint32_t (&b)[2]) {
    asm volatile(
        "mma.sync.aligned.m16n8k16.row.col.f32.bf16.bf16.f32 "
        "{%0,%1,%2,%3}, {%4,%5,%6,%7}, {%8,%9}, {%0,%1,%2,%3};"
        : "+f"(d[0]), "+f"(d[1]), "+f"(d[2]), "+f"(d[3])
        : "r"(a[0]), "r"(a[1]), "r"(a[2]), "r"(a[3]), "r"(b[0]), "r"(b[1]));
}
// pack two f32 into bf16x2 (lo = v0, hi = v1), return residuals
__device__ __forceinline__ uint32_t pack_hi(float v0, float v1) {
    uint32_t hp;
    asm("cvt.rn.bf16x2.f32 %0, %1, %2;" : "=r"(hp) : "f"(v1), "f"(v0));
    return hp;
}

// ---------------------------------------------------------------------------
// Kernel 1: routing MLP + softmax -> g_att
// ---------------------------------------------------------------------------
__global__ void att_kernel(const float* __restrict__ cond,
                           const float* __restrict__ w1,
                           const float* __restrict__ w2) {
    int b = blockIdx.x;
    int j = threadIdx.x;  // 0..63
    __shared__ float h[HIDC];
    __shared__ float logits[4];

    const float* cb  = cond + b * CSC;
    const float* w1j = w1 + j * CSC;
    float acc = 0.f;
    #pragma unroll 8
    for (int c = 0; c < CSC; c++) acc = fmaf(w1j[c], cb[c], acc);
    h[j] = fmaxf(acc, 0.f);
    __syncthreads();

    if (j < 4) {
        const float* w2j = w2 + j * HIDC;
        float s = 0.f;
        #pragma unroll 8
        for (int c = 0; c < HIDC; c++) s = fmaf(w2j[c], h[c], s);
        logits[j] = s / TEMPR;
    }
    __syncthreads();

    if (j == 0) {
        float m = fmaxf(fmaxf(logits[0], logits[1]), fmaxf(logits[2], logits[3]));
        float e[4]; float ssum = 0.f;
        #pragma unroll
        for (int k = 0; k < 4; k++) { e[k] = expf(logits[k] - m); ssum += e[k]; }
        float inv = 1.f / ssum;
        #pragma unroll
        for (int k = 0; k < 4; k++) g_att[b * 4 + k] = e[k] * inv;
    }
}

// ---------------------------------------------------------------------------
// Kernel 2: expert aggregation -> g_wh/g_wl, layout [b][t][o][i]
//   value = sum_e att[b][e] * W[e][o][i][t][1]   (middle kernel column)
// Thread owns one (t, o, i-pair), loops over 64 samples.  Stores coalesced.
// ---------------------------------------------------------------------------
__global__ __launch_bounds__(256) void agg_kernel(const float* __restrict__ weight) {
    __shared__ float satt[NB * 4];
    int tid = threadIdx.x;
    satt[tid] = g_att[tid];   // 256 == NB*4
    __syncthreads();

    int pos = blockIdx.x * 256 + tid;   // 0 .. 98303 = 3*256*128
    int t  = pos >> 15;                 // 0..2
    int o  = (pos >> 7) & 255;
    int ip = pos & 127;
    int i  = ip * 2;

    float w[2][4];
    const size_t es = (size_t)COUTC * CINC * 9;
    #pragma unroll
    for (int q = 0; q < 2; q++) {
        size_t base = ((size_t)o * CINC + i + q) * 9 + t * 3 + 1;
        #pragma unroll
        for (int e = 0; e < 4; e++) w[q][e] = __ldg(weight + base + (size_t)e * es);
    }

    for (int b = 0; b < NB; b++) {
        float a0 = satt[b * 4 + 0], a1 = satt[b * 4 + 1];
        float a2 = satt[b * 4 + 2], a3 = satt[b * 4 + 3];
        float v0 = fmaf(a3, w[0][3], fmaf(a2, w[0][2], fmaf(a1, w[0][1], a0 * w[0][0])));
        float v1 = fmaf(a3, w[1][3], fmaf(a2, w[1][2], fmaf(a1, w[1][1], a0 * w[1][0])));
        uint32_t hp = pack_hi(v0, v1);
        float h0 = __uint_as_float(hp << 16);
        float h1 = __uint_as_float(hp & 0xFFFF0000u);
        uint32_t lp = pack_hi(v0 - h0, v1 - h1);
        size_t idx = ((size_t)(b * 3 + t) * COUTC + o) * CINC + i;   // 4B aligned
        *reinterpret_cast<uint32_t*>(&g_wh[idx]) = hp;
        *reinterpret_cast<uint32_t*>(&g_wl[idx]) = lp;
    }
}

// ---------------------------------------------------------------------------
// Kernel 3: batched GEMM via mma.sync m16n8k16 bf16 (hi/lo compensated)
//   out[b][o][l] = bias_agg[b][o] + sum_t sum_i Wagg[b][t][o][i] * x[b][i][l+t-1]
// Block: 128(o) x 128(l); 8 warps as 2(m) x 4(n); warp tile 64 x 32.
// Grid: (16, 64): x -> (otile = x&1, ltile = x>>1), y -> sample.
// ---------------------------------------------------------------------------
__global__ __launch_bounds__(256, 1)
void gemm_kernel(const float* __restrict__ x,
                 const float* __restrict__ bias,
                 float* __restrict__ out) {
    extern __shared__ char smem[];
    const int tid  = threadIdx.x;
    const int lane = tid & 31, wid = tid >> 5;
    const int wm = wid & 1, wn = wid >> 1;
    const int bq = blockIdx.y;
    const int o0 = (blockIdx.x & 1) * BM;
    const int l0 = (blockIdx.x >> 1) * BN;
    const uint32_t sb = smem_u32(smem);

    // aggregated bias for this block's 128 output channels
    if (tid < BM) {
        float a0 = g_att[bq * 4 + 0], a1 = g_att[bq * 4 + 1];
        float a2 = g_att[bq * 4 + 2], a3 = g_att[bq * 4 + 3];
        int o = o0 + tid;
        ((float*)smem)[tid] =
            fmaf(a3, bias[3 * COUTC + o], fmaf(a2, bias[2 * COUTC + o],
            fmaf(a1, bias[1 * COUTC + o], a0 * bias[o])));
    }

    float acc[4][4][4];
    #pragma unroll
    for (int mf = 0; mf < 4; mf++)
        #pragma unroll
        for (int nf = 0; nf < 4; nf++)
            #pragma unroll
            for (int q = 0; q < 4; q++) acc[mf][nf][q] = 0.f;

    // ldmatrix lane-derived offsets
    const uint32_t aro = (lane & 7) + ((lane >> 3) & 1) * 8;  // A row offset
    const uint32_t ako = (lane >> 4) * 16;                    // A k byte offset
    const uint32_t bro = (lane & 7) + ((lane >> 4) & 1) * 8;  // B row offset
    const uint32_t bko = ((lane >> 3) & 1) * 16;              // B k byte offset

    const float* xb = x + (size_t)bq * CINC * LDIMC;
    const __nv_bfloat16* whb = g_wh + (size_t)bq * 3 * COUTC * CINC;
    const __nv_bfloat16* wlb = g_wl + (size_t)bq * 3 * COUTC * CINC;
    const int ipg = tid >> 5;       // x-fill: i-pair group
    const int lng = tid & 31;       // x-fill: lane -> l

    for (int ic = 0; ic < NCH; ic++) {
        __syncthreads();  // previous chunk fully consumed (also covers bagg)

        // ---- A fill: 6 tiles (3 taps x hi/lo), 128 rows x 64B, pad to 80B ----
        #pragma unroll
        for (int j = 0; j < 12; j++) {
            int u = tid + 256 * j;
            int tile = u >> 9, rem = u & 511;
            int row = rem >> 2, seg = rem & 3;
            int tap = tile >> 1, hsel = tile & 1;
            const __nv_bfloat16* src = (hsel ? wlb : whb)
                + ((size_t)tap * COUTC + o0 + row) * CINC + ic * IC + seg * 8;
            *(uint4*)(smem + OFF_A + tile * ATS + row * 80 + seg * 16) =
                *(const uint4*)src;
        }

        // ---- X fill: 130 rows (l0-1..l0+128) x 32 i, hi/lo split on the fly ----
        #pragma unroll
        for (int r = 0; r < 5; r++) {
            int lp = lng + 32 * r;
            if (lp < 130) {
                int gl = l0 - 1 + lp;
                bool ok = (gl >= 0) && (gl < LDIMC);
                #pragma unroll
                for (int q = 0; q < 2; q++) {
                    int ip = ipg + 8 * q;
                    size_t gi = (size_t)(ic * IC + 2 * ip) * LDIMC + gl;
                    float v0 = ok ? __ldg(xb + gi) : 0.f;
                    float v1 = ok ? __ldg(xb + gi + LDIMC) : 0.f;
                    uint32_t hp = pack_hi(v0, v1);
                    float h0 = __uint_as_float(hp << 16);
                    float h1 = __uint_as_float(hp & 0xFFFF0000u);
                    uint32_t lo = pack_hi(v0 - h0, v1 - h1);
                    *(uint32_t*)(smem + OFF_XH + lp * 80 + ip * 4) = hp;
                    *(uint32_t*)(smem + OFF_XL + lp * 80 + ip * 4) = lo;
                }
            }
        }
        __syncthreads();

        // ---- compute: 2 k16-steps x 3 taps x (4 mf x 4 nf x 3 products) ----
        #pragma unroll
        for (int ks = 0; ks < 2; ks++) {
            #pragma unroll
            for (int tap = 0; tap < 3; tap++) {
                uint32_t bh[4][2], bl[4][2];
                #pragma unroll
                for (int np = 0; np < 2; np++) {
                    uint32_t rr[4];
                    uint32_t rowb = tap + wn * 32 + np * 16 + bro;
                    ldsm4(rr, sb + OFF_XH + rowb * 80 + ks * 32 + bko);
                    bh[np * 2][0] = rr[0]; bh[np * 2][1] = rr[1];
                    bh[np * 2 + 1][0] = rr[2]; bh[np * 2 + 1][1] = rr[3];
                    ldsm4(rr, sb + OFF_XL + rowb * 80 + ks * 32 + bko);
                    bl[np * 2][0] = rr[0]; bl[np * 2][1] = rr[1];
                    bl[np * 2 + 1][0] = rr[2]; bl[np * 2 + 1][1] = rr[3];
                }
                #pragma unroll
                for (int mf = 0; mf < 4; mf++) {
                    uint32_t ah[4], al[4];
                    uint32_t rowa = wm * 64 + mf * 16 + aro;
                    ldsm4(ah, sb + OFF_A + (tap * 2 + 0) * ATS + rowa * 80 + ks * 32 + ako);
                    ldsm4(al, sb + OFF_A + (tap * 2 + 1) * ATS + rowa * 80 + ks * 32 + ako);
                    #pragma unroll
                    for (int nf = 0; nf < 4; nf++) mma16816(acc[mf][nf], ah, bh[nf]);
                    #pragma unroll
                    for (int nf = 0; nf < 4; nf++) mma16816(acc[mf][nf], al, bh[nf]);
                    #pragma unroll
                    for (int nf = 0; nf < 4; nf++) mma16816(acc[mf][nf], ah, bl[nf]);
                }
            }
        }
    }

    // ---- epilogue: fragments + bias -> global (each 4-lane group = 32B sector)
    const float* bagg = (const float*)smem;
    #pragma unroll
    for (int mf = 0; mf < 4; mf++) {
        int rl = wm * 64 + mf * 16 + (lane >> 2);
        float b0 = bagg[rl], b1 = bagg[rl + 8];
        size_t ro0 = ((size_t)bq * COUTC + o0 + rl) * LDIMC;
        size_t ro1 = ro0 + 8 * LDIMC;
        #pragma unroll
        for (int nf = 0; nf < 4; nf++) {
            int c = l0 + wn * 32 + nf * 8 + 2 * (lane & 3);
            float2 v0 = make_float2(acc[mf][nf][0] + b0, acc[mf][nf][1] + b0);
            float2 v1 = make_float2(acc[mf][nf][2] + b1, acc[mf][nf][3] + b1);
            *(float2*)(out + ro0 + c) = v0;
            *(float2*)(out + ro1 + c) = v1;
        }
    }
}

// ---------------------------------------------------------------------------
extern "C" void kernel_launch(void* const* d_in, const int* in_sizes, int n_in,
                              void* d_out, int out_size) {
    const float* x      = (const float*)d_in[0];  // (64,256,1024,1)
    const float* cond   = (const float*)d_in[1];  // (64,256)
    const float* w1     = (const float*)d_in[2];  // (64,256)
    const float* w2     = (const float*)d_in[3];  // (4,64)
    const float* weight = (const float*)d_in[4];  // (4,256,256,3,3)
    const float* bias   = (const float*)d_in[5];  // (4,256)
    float* out = (float*)d_out;                   // (64,256,1024,1)

    cudaFuncSetAttribute(gemm_kernel, cudaFuncAttributeMaxDynamicSharedMemorySize,
                         SMEMSZ);

    att_kernel<<<NB, HIDC>>>(cond, w1, w2);
    agg_kernel<<<384, 256>>>(weight);
    dim3 grid(16, NB);
    gemm_kernel<<<grid, 256, SMEMSZ>>>(x, bias, out);
}

// round 8
// speedup vs baseline: 5.3207x; 1.2536x over previous
#include <cuda_runtime.h>
#include <cuda_bf16.h>
#include <cstdint>

// ---------------- problem constants ----------------
#define NB     64
#define CINC   256
#define COUTC  256
#define CSC    256
#define HIDC   64
#define LDIMC  1024
#define TEMPR  30.0f

// ---------------- GEMM tiling ----------------
#define BM   128          // o per block
#define BN   128          // l per block
#define IC   32           // input channels per chunk
#define NCH  8            // CINC / IC

// ---------------- smem map (dynamic) ----------------
// [0,512)               : aggregated bias (128 floats)
// [512, +2*61440)       : A stages; each = 6 tiles (tap x hi/lo) of 128rows x 80B
// [123392, +2*20800)    : X stages; each = hi(130x80B) + lo(130x80B)
#define OFF_A   512
#define ATILE   10240
#define AST     61440
#define OFF_X   123392
#define XST     20800
#define SMEMSZ  164992

// ---------------- device scratch ----------------
__device__ float g_att[NB * 4];
// aggregated weights, layout [b][tap][o][i], bf16 hi + bf16 residual
__device__ __align__(16) __nv_bfloat16 g_wh[(size_t)NB * 3 * COUTC * CINC];
__device__ __align__(16) __nv_bfloat16 g_wl[(size_t)NB * 3 * COUTC * CINC];

// ---------------- helpers ----------------
__device__ __forceinline__ uint32_t smem_u32(const void* p) {
    uint32_t a;
    asm("{ .reg .u64 t; cvta.to.shared.u64 t, %1; cvt.u32.u64 %0, t; }" : "=r"(a) : "l"(p));
    return a;
}
__device__ __forceinline__ void ldsm4(uint32_t (&r)[4], uint32_t addr) {
    asm volatile("ldmatrix.sync.aligned.m8n8.x4.shared.b16 {%0,%1,%2,%3}, [%4];"
                 : "=r"(r[0]), "=r"(r[1]), "=r"(r[2]), "=r"(r[3]) : "r"(addr));
}
__device__ __forceinline__ void mma16816(float (&d)[4], const uint32_t (&a)[4],
                                         const uint32_t (&b)[2]) {
    asm volatile(
        "mma.sync.aligned.m16n8k16.row.col.f32.bf16.bf16.f32 "
        "{%0,%1,%2,%3}, {%4,%5,%6,%7}, {%8,%9}, {%0,%1,%2,%3};"
        : "+f"(d[0]), "+f"(d[1]), "+f"(d[2]), "+f"(d[3])
        : "r"(a[0]), "r"(a[1]), "r"(a[2]), "r"(a[3]), "r"(b[0]), "r"(b[1]));
}
__device__ __forceinline__ uint32_t pack_hi(float v0, float v1) {
    uint32_t hp;
    asm("cvt.rn.bf16x2.f32 %0, %1, %2;" : "=r"(hp) : "f"(v1), "f"(v0));
    return hp;
}
__device__ __forceinline__ void cp_async16(uint32_t dst, const void* src) {
    asm volatile("cp.async.cg.shared.global [%0], [%1], 16;" :: "r"(dst), "l"(src));
}
#define CP_COMMIT() asm volatile("cp.async.commit_group;" ::: "memory")
#define CP_WAIT0()  asm volatile("cp.async.wait_group 0;" ::: "memory")

// ---------------------------------------------------------------------------
// Kernel 1: routing MLP + softmax -> g_att.  256 threads per sample.
// Warp w computes h[w*8 .. w*8+7] via 32-lane split dots + shfl reduce.
// ---------------------------------------------------------------------------
__global__ __launch_bounds__(256) void att_kernel(const float* __restrict__ cond,
                                                  const float* __restrict__ w1,
                                                  const float* __restrict__ w2) {
    int b = blockIdx.x;
    int tid = threadIdx.x;
    int w = tid >> 5, l = tid & 31;
    __shared__ float sc[CSC];
    __shared__ float h[HIDC];
    __shared__ float logits[4];

    sc[tid] = cond[b * CSC + tid];
    __syncthreads();

    #pragma unroll
    for (int jj = 0; jj < 8; jj++) {
        int j = w * 8 + jj;
        const float* r = w1 + j * CSC;
        float a = 0.f;
        #pragma unroll
        for (int q = 0; q < 8; q++) a = fmaf(__ldg(r + l + 32 * q), sc[l + 32 * q], a);
        #pragma unroll
        for (int off = 16; off >= 1; off >>= 1)
            a += __shfl_xor_sync(0xFFFFFFFFu, a, off);
        if (l == 0) h[j] = fmaxf(a, 0.f);
    }
    __syncthreads();

    if (w == 0) {
        #pragma unroll
        for (int j = 0; j < 4; j++) {
            float a = fmaf(__ldg(w2 + j * HIDC + l), h[l],
                           __ldg(w2 + j * HIDC + 32 + l) * h[32 + l]);
            #pragma unroll
            for (int off = 16; off >= 1; off >>= 1)
                a += __shfl_xor_sync(0xFFFFFFFFu, a, off);
            if (l == 0) logits[j] = a / TEMPR;
        }
        __syncwarp();
        if (l == 0) {
            float m = fmaxf(fmaxf(logits[0], logits[1]), fmaxf(logits[2], logits[3]));
            float e[4]; float ssum = 0.f;
            #pragma unroll
            for (int k = 0; k < 4; k++) { e[k] = expf(logits[k] - m); ssum += e[k]; }
            float inv = 1.f / ssum;
            #pragma unroll
            for (int k = 0; k < 4; k++) g_att[b * 4 + k] = e[k] * inv;
        }
    }
}

// ---------------------------------------------------------------------------
// Kernel 2: expert aggregation -> g_wh/g_wl, layout [b][t][o][i]
// ---------------------------------------------------------------------------
__global__ __launch_bounds__(256) void agg_kernel(const float* __restrict__ weight) {
    __shared__ float satt[NB * 4];
    int tid = threadIdx.x;
    satt[tid] = g_att[tid];   // 256 == NB*4
    __syncthreads();

    int pos = blockIdx.x * 256 + tid;   // 0 .. 98303 = 3*256*128
    int t  = pos >> 15;
    int o  = (pos >> 7) & 255;
    int ip = pos & 127;
    int i  = ip * 2;

    float w[2][4];
    const size_t es = (size_t)COUTC * CINC * 9;
    #pragma unroll
    for (int q = 0; q < 2; q++) {
        size_t base = ((size_t)o * CINC + i + q) * 9 + t * 3 + 1;
        #pragma unroll
        for (int e = 0; e < 4; e++) w[q][e] = __ldg(weight + base + (size_t)e * es);
    }

    for (int b = 0; b < NB; b++) {
        float a0 = satt[b * 4 + 0], a1 = satt[b * 4 + 1];
        float a2 = satt[b * 4 + 2], a3 = satt[b * 4 + 3];
        float v0 = fmaf(a3, w[0][3], fmaf(a2, w[0][2], fmaf(a1, w[0][1], a0 * w[0][0])));
        float v1 = fmaf(a3, w[1][3], fmaf(a2, w[1][2], fmaf(a1, w[1][1], a0 * w[1][0])));
        uint32_t hp = pack_hi(v0, v1);
        float h0 = __uint_as_float(hp << 16);
        float h1 = __uint_as_float(hp & 0xFFFF0000u);
        uint32_t lp = pack_hi(v0 - h0, v1 - h1);
        size_t idx = ((size_t)(b * 3 + t) * COUTC + o) * CINC + i;
        *reinterpret_cast<uint32_t*>(&g_wh[idx]) = hp;
        *reinterpret_cast<uint32_t*>(&g_wl[idx]) = lp;
    }
}

// ---------------------------------------------------------------------------
// Kernel 3: batched GEMM via mma.sync m16n8k16 bf16 (hi/lo compensated),
// software-pipelined: cp.async double-buffered A, register-prefetched X.
// ---------------------------------------------------------------------------
__global__ __launch_bounds__(256, 1)
void gemm_kernel(const float* __restrict__ x,
                 const float* __restrict__ bias,
                 float* __restrict__ out) {
    extern __shared__ char smem[];
    const int tid  = threadIdx.x;
    const int lane = tid & 31, wid = tid >> 5;
    const int wm = wid & 1, wn = wid >> 1;
    const int bq = blockIdx.y;
    const int o0 = (blockIdx.x & 1) * BM;
    const int l0 = (blockIdx.x >> 1) * BN;
    const uint32_t sb = smem_u32(smem);

    // aggregated bias for this block's 128 output channels
    if (tid < BM) {
        float a0 = g_att[bq * 4 + 0], a1 = g_att[bq * 4 + 1];
        float a2 = g_att[bq * 4 + 2], a3 = g_att[bq * 4 + 3];
        int o = o0 + tid;
        ((float*)smem)[tid] =
            fmaf(a3, bias[3 * COUTC + o], fmaf(a2, bias[2 * COUTC + o],
            fmaf(a1, bias[1 * COUTC + o], a0 * bias[o])));
    }

    float acc[4][4][4];
    #pragma unroll
    for (int mf = 0; mf < 4; mf++)
        #pragma unroll
        for (int nf = 0; nf < 4; nf++)
            #pragma unroll
            for (int q = 0; q < 4; q++) acc[mf][nf][q] = 0.f;

    const uint32_t aro = (lane & 7) + ((lane >> 3) & 1) * 8;
    const uint32_t ako = (lane >> 4) * 16;
    const uint32_t bro = (lane & 7) + ((lane >> 4) & 1) * 8;
    const uint32_t bko = ((lane >> 3) & 1) * 16;

    const float* xb = x + (size_t)bq * CINC * LDIMC;
    const __nv_bfloat16* whb = g_wh + (size_t)bq * 3 * COUTC * CINC;
    const __nv_bfloat16* wlb = g_wl + (size_t)bq * 3 * COUTC * CINC;
    const int ipg = tid >> 5;   // x-fill: i-pair group (0..7)
    const int lng = tid & 31;   // x-fill: lane -> l

    float xr[5][2][2];

    // ---- fill helpers (inlined via lambdas) ----
    auto fillA = [&](int ic, int s) {
        #pragma unroll
        for (int j = 0; j < 12; j++) {
            int u = tid + 256 * j;
            int tile = u >> 9, rem = u & 511;
            int row = rem >> 2, seg = rem & 3;
            int tap = tile >> 1, hsel = tile & 1;
            const __nv_bfloat16* src = (hsel ? wlb : whb)
                + ((size_t)tap * COUTC + o0 + row) * CINC + ic * IC + seg * 8;
            cp_async16(sb + OFF_A + s * AST + tile * ATILE + row * 80 + seg * 16, src);
        }
    };
    auto ldgX = [&](int ic) {
        #pragma unroll
        for (int r = 0; r < 5; r++) {
            int lp = lng + 32 * r;
            int gl = l0 - 1 + lp;
            bool ok = (lp < 130) && (gl >= 0) && (gl < LDIMC);
            #pragma unroll
            for (int q = 0; q < 2; q++) {
                size_t gi = (size_t)(ic * IC + 2 * (ipg + 8 * q)) * LDIMC + gl;
                xr[r][q][0] = ok ? __ldg(xb + gi) : 0.f;
                xr[r][q][1] = ok ? __ldg(xb + gi + LDIMC) : 0.f;
            }
        }
    };
    auto stsX = [&](int s) {
        char* xh = smem + OFF_X + s * XST;
        char* xl = xh + 10400;
        #pragma unroll
        for (int r = 0; r < 5; r++) {
            int lp = lng + 32 * r;
            if (lp < 130) {
                #pragma unroll
                for (int q = 0; q < 2; q++) {
                    int ip = ipg + 8 * q;
                    float v0 = xr[r][q][0], v1 = xr[r][q][1];
                    uint32_t hp = pack_hi(v0, v1);
                    float h0 = __uint_as_float(hp << 16);
                    float h1 = __uint_as_float(hp & 0xFFFF0000u);
                    uint32_t lo = pack_hi(v0 - h0, v1 - h1);
                    *(uint32_t*)(xh + lp * 80 + ip * 4) = hp;
                    *(uint32_t*)(xl + lp * 80 + ip * 4) = lo;
                }
            }
        }
    };

    // ---- prologue: stage 0 ----
    fillA(0, 0); CP_COMMIT();
    ldgX(0);
    CP_WAIT0();
    stsX(0);
    __syncthreads();

    for (int ic = 0; ic < NCH; ic++) {
        const int s = ic & 1;
        if (ic + 1 < NCH) {
            fillA(ic + 1, s ^ 1); CP_COMMIT();
            ldgX(ic + 1);
        }

        // ---- compute on stage s ----
        const uint32_t aA = sb + OFF_A + s * AST;
        const uint32_t aXH = sb + OFF_X + s * XST;
        const uint32_t aXL = aXH + 10400;
        #pragma unroll
        for (int ks = 0; ks < 2; ks++) {
            #pragma unroll
            for (int tap = 0; tap < 3; tap++) {
                uint32_t bh[4][2], bl[4][2];
                #pragma unroll
                for (int np = 0; np < 2; np++) {
                    uint32_t rr[4];
                    uint32_t rowb = tap + wn * 32 + np * 16 + bro;
                    ldsm4(rr, aXH + rowb * 80 + ks * 32 + bko);
                    bh[np * 2][0] = rr[0]; bh[np * 2][1] = rr[1];
                    bh[np * 2 + 1][0] = rr[2]; bh[np * 2 + 1][1] = rr[3];
                    ldsm4(rr, aXL + rowb * 80 + ks * 32 + bko);
                    bl[np * 2][0] = rr[0]; bl[np * 2][1] = rr[1];
                    bl[np * 2 + 1][0] = rr[2]; bl[np * 2 + 1][1] = rr[3];
                }
                #pragma unroll
                for (int mf = 0; mf < 4; mf++) {
                    uint32_t ah[4], al[4];
                    uint32_t rowa = wm * 64 + mf * 16 + aro;
                    ldsm4(ah, aA + (tap * 2 + 0) * ATILE + rowa * 80 + ks * 32 + ako);
                    ldsm4(al, aA + (tap * 2 + 1) * ATILE + rowa * 80 + ks * 32 + ako);
                    #pragma unroll
                    for (int nf = 0; nf < 4; nf++) mma16816(acc[mf][nf], ah, bh[nf]);
                    #pragma unroll
                    for (int nf = 0; nf < 4; nf++) mma16816(acc[mf][nf], al, bh[nf]);
                    #pragma unroll
                    for (int nf = 0; nf < 4; nf++) mma16816(acc[mf][nf], ah, bl[nf]);
                }
            }
        }

        if (ic + 1 < NCH) {
            CP_WAIT0();
            stsX(s ^ 1);
        }
        __syncthreads();
    }

    // ---- epilogue: fragments + bias -> global ----
    const float* bagg = (const float*)smem;
    #pragma unroll
    for (int mf = 0; mf < 4; mf++) {
        int rl = wm * 64 + mf * 16 + (lane >> 2);
        float b0 = bagg[rl], b1 = bagg[rl + 8];
        size_t ro0 = ((size_t)bq * COUTC + o0 + rl) * LDIMC;
        size_t ro1 = ro0 + 8 * LDIMC;
        #pragma unroll
        for (int nf = 0; nf < 4; nf++) {
            int c = l0 + wn * 32 + nf * 8 + 2 * (lane & 3);
            float2 v0 = make_float2(acc[mf][nf][0] + b0, acc[mf][nf][1] + b0);
            float2 v1 = make_float2(acc[mf][nf][2] + b1, acc[mf][nf][3] + b1);
            *(float2*)(out + ro0 + c) = v0;
            *(float2*)(out + ro1 + c) = v1;
        }
    }
}

// ---------------------------------------------------------------------------
extern "C" void kernel_launch(void* const* d_in, const int* in_sizes, int n_in,
                              void* d_out, int out_size) {
    const float* x      = (const float*)d_in[0];  // (64,256,1024,1)
    const float* cond   = (const float*)d_in[1];  // (64,256)
    const float* w1     = (const float*)d_in[2];  // (64,256)
    const float* w2     = (const float*)d_in[3];  // (4,64)
    const float* weight = (const float*)d_in[4];  // (4,256,256,3,3)
    const float* bias   = (const float*)d_in[5];  // (4,256)
    float* out = (float*)d_out;                   // (64,256,1024,1)

    cudaFuncSetAttribute(gemm_kernel, cudaFuncAttributeMaxDynamicSharedMemorySize,
                         SMEMSZ);

    att_kernel<<<NB, 256>>>(cond, w1, w2);
    agg_kernel<<<384, 256>>>(weight);
    dim3 grid(16, NB);
    gemm_kernel<<<grid, 256, SMEMSZ>>>(x, bias, out);
}

// round 10
// speedup vs baseline: 5.3337x; 1.0024x over previous
#include <cuda_runtime.h>
#include <cuda_bf16.h>
#include <cstdint>

// ---------------- problem constants ----------------
#define NB     64
#define CINC   256
#define COUTC  256
#define CSC    256
#define HIDC   64
#define LDIMC  1024
#define TEMPR  30.0f

// ---------------- GEMM tiling ----------------
#define BM   128          // o per block
#define BN   128          // l per block
#define IC   16           // input channels per chunk
#define NCH  16           // CINC / IC

// ---------------- smem map (dynamic) ----------------
// [0,512)            : aggregated bias (128 floats)
// [512, +2*36864)    : A stages; each = 6 tiles (tap x hi/lo) of 128 rows x 48B
// [74240, +2*12480)  : X stages; each = hi(130x48B) + lo(130x48B)
#define OFF_A   512
#define ATILE   6144
#define AST     36864
#define OFF_X   74240
#define XST     12480
#define SMEMSZ  99200

// ---------------- device scratch ----------------
__device__ float g_att[NB * 4];
// aggregated weights pre-swizzled into gemm consumption order:
// [b][ot(2)][ic(16)][tap(3)][hl(2)][row(128)][ch(16)] bf16
__device__ __align__(16) __nv_bfloat16 g_w[(size_t)NB * 2 * 16 * 6 * 128 * 16];

// ---------------- helpers ----------------
__device__ __forceinline__ uint32_t smem_u32(const void* p) {
    uint32_t a;
    asm("{ .reg .u64 t; cvta.to.shared.u64 t, %1; cvt.u32.u64 %0, t; }" : "=r"(a) : "l"(p));
    return a;
}
__device__ __forceinline__ void ldsm4(uint32_t (&r)[4], uint32_t addr) {
    asm volatile("ldmatrix.sync.aligned.m8n8.x4.shared.b16 {%0,%1,%2,%3}, [%4];"
                 : "=r"(r[0]), "=r"(r[1]), "=r"(r[2]), "=r"(r[3]) : "r"(addr));
}
__device__ __forceinline__ void mma16816(float (&d)[4], const uint32_t (&a)[4],
                                         const uint32_t (&b)[2]) {
    asm volatile(
        "mma.sync.aligned.m16n8k16.row.col.f32.bf16.bf16.f32 "
        "{%0,%1,%2,%3}, {%4,%5,%6,%7}, {%8,%9}, {%0,%1,%2,%3};"
        : "+f"(d[0]), "+f"(d[1]), "+f"(d[2]), "+f"(d[3])
        : "r"(a[0]), "r"(a[1]), "r"(a[2]), "r"(a[3]), "r"(b[0]), "r"(b[1]));
}
__device__ __forceinline__ uint32_t pack_hi(float v0, float v1) {
    uint32_t hp;
    asm("cvt.rn.bf16x2.f32 %0, %1, %2;" : "=r"(hp) : "f"(v1), "f"(v0));
    return hp;
}
__device__ __forceinline__ void cp_async16(uint32_t dst, const void* src) {
    asm volatile("cp.async.cg.shared.global [%0], [%1], 16;" :: "r"(dst), "l"(src));
}
#define CP_COMMIT() asm volatile("cp.async.commit_group;" ::: "memory")
#define CP_WAIT0()  asm volatile("cp.async.wait_group 0;" ::: "memory")

// ---------------------------------------------------------------------------
// Kernel 1: routing MLP + softmax -> g_att
// ---------------------------------------------------------------------------
__global__ __launch_bounds__(256) void att_kernel(const float* __restrict__ cond,
                                                  const float* __restrict__ w1,
                                                  const float* __restrict__ w2) {
    int b = blockIdx.x;
    int tid = threadIdx.x;
    int w = tid >> 5, l = tid & 31;
    __shared__ float sc[CSC];
    __shared__ float h[HIDC];
    __shared__ float logits[4];

    sc[tid] = cond[b * CSC + tid];
    __syncthreads();

    #pragma unroll
    for (int jj = 0; jj < 8; jj++) {
        int j = w * 8 + jj;
        const float* r = w1 + j * CSC;
        float a = 0.f;
        #pragma unroll
        for (int q = 0; q < 8; q++) a = fmaf(__ldg(r + l + 32 * q), sc[l + 32 * q], a);
        #pragma unroll
        for (int off = 16; off >= 1; off >>= 1)
            a += __shfl_xor_sync(0xFFFFFFFFu, a, off);
        if (l == 0) h[j] = fmaxf(a, 0.f);
    }
    __syncthreads();

    if (w == 0) {
        #pragma unroll
        for (int j = 0; j < 4; j++) {
            float a = fmaf(__ldg(w2 + j * HIDC + l), h[l],
                           __ldg(w2 + j * HIDC + 32 + l) * h[32 + l]);
            #pragma unroll
            for (int off = 16; off >= 1; off >>= 1)
                a += __shfl_xor_sync(0xFFFFFFFFu, a, off);
            if (l == 0) logits[j] = a / TEMPR;
        }
        __syncwarp();
        if (l == 0) {
            float m = fmaxf(fmaxf(logits[0], logits[1]), fmaxf(logits[2], logits[3]));
            float e[4]; float ssum = 0.f;
            #pragma unroll
            for (int k = 0; k < 4; k++) { e[k] = expf(logits[k] - m); ssum += e[k]; }
            float inv = 1.f / ssum;
            #pragma unroll
            for (int k = 0; k < 4; k++) g_att[b * 4 + k] = e[k] * inv;
        }
    }
}

// ---------------------------------------------------------------------------
// Kernel 2: expert aggregation -> g_w (hi + residual bf16), pre-swizzled into
// the gemm's tile consumption order.
// Thread owns (t, o, i-pair); loops over the 64 samples.
// ---------------------------------------------------------------------------
__global__ __launch_bounds__(256) void agg_kernel(const float* __restrict__ weight) {
    __shared__ float satt[NB * 4];
    int tid = threadIdx.x;
    satt[tid] = g_att[tid];   // 256 == NB*4
    __syncthreads();

    int pos = blockIdx.x * 256 + tid;   // 0 .. 98303 = 3*256*128
    int t  = pos >> 15;
    int o  = (pos >> 7) & 255;
    int ip = pos & 127;
    int i  = ip * 2;

    int ot = o >> 7, row = o & 127;
    int icc = i >> 4, ch = i & 15;

    float w[2][4];
    const size_t es = (size_t)COUTC * CINC * 9;
    #pragma unroll
    for (int q = 0; q < 2; q++) {
        size_t base = ((size_t)o * CINC + i + q) * 9 + t * 3 + 1;
        #pragma unroll
        for (int e = 0; e < 4; e++) w[q][e] = __ldg(weight + base + (size_t)e * es);
    }

    for (int b = 0; b < NB; b++) {
        float a0 = satt[b * 4 + 0], a1 = satt[b * 4 + 1];
        float a2 = satt[b * 4 + 2], a3 = satt[b * 4 + 3];
        float v0 = fmaf(a3, w[0][3], fmaf(a2, w[0][2], fmaf(a1, w[0][1], a0 * w[0][0])));
        float v1 = fmaf(a3, w[1][3], fmaf(a2, w[1][2], fmaf(a1, w[1][1], a0 * w[1][0])));
        uint32_t hp = pack_hi(v0, v1);
        float h0 = __uint_as_float(hp << 16);
        float h1 = __uint_as_float(hp & 0xFFFF0000u);
        uint32_t lp = pack_hi(v0 - h0, v1 - h1);
        // tile index = tap*2 + hl
        size_t base = ((((size_t)(b * 2 + ot) * 16 + icc) * 6) + t * 2) * 2048
                    + row * 16 + ch;
        *reinterpret_cast<uint32_t*>(&g_w[base])        = hp;   // hl=0
        *reinterpret_cast<uint32_t*>(&g_w[base + 2048]) = lp;   // hl=1
    }
}

// ---------------------------------------------------------------------------
// Kernel 3: batched GEMM via mma.sync m16n8k16 bf16 (hi/lo compensated).
// Double-buffered A (cp.async, fully coalesced from pre-swizzled g_w) and
// X (register-prefetched LDG, converted post-MMA).  2 CTAs/SM.
// ---------------------------------------------------------------------------
__global__ __launch_bounds__(256, 2)
void gemm_kernel(const float* __restrict__ x,
                 const float* __restrict__ bias,
                 float* __restrict__ out) {
    extern __shared__ char smem[];
    const int tid  = threadIdx.x;
    const int lane = tid & 31, wid = tid >> 5;
    const int wm = wid & 1, wn = wid >> 1;
    const int bq = blockIdx.y;
    const int ot = blockIdx.x & 1;
    const int o0 = ot * BM;
    const int l0 = (blockIdx.x >> 1) * BN;
    const uint32_t sb = smem_u32(smem);

    if (tid < BM) {
        float a0 = g_att[bq * 4 + 0], a1 = g_att[bq * 4 + 1];
        float a2 = g_att[bq * 4 + 2], a3 = g_att[bq * 4 + 3];
        int o = o0 + tid;
        ((float*)smem)[tid] =
            fmaf(a3, bias[3 * COUTC + o], fmaf(a2, bias[2 * COUTC + o],
            fmaf(a1, bias[1 * COUTC + o], a0 * bias[o])));
    }

    float acc[4][4][4];
    #pragma unroll
    for (int mf = 0; mf < 4; mf++)
        #pragma unroll
        for (int nf = 0; nf < 4; nf++)
            #pragma unroll
            for (int q = 0; q < 4; q++) acc[mf][nf][q] = 0.f;

    const uint32_t aro = (lane & 7) + ((lane >> 3) & 1) * 8;
    const uint32_t ako = (lane >> 4) * 16;
    const uint32_t bro = (lane & 7) + ((lane >> 4) & 1) * 8;
    const uint32_t bko = ((lane >> 3) & 1) * 16;

    const float* xb = x + (size_t)bq * CINC * LDIMC;
    // per-(b, otile) weight slab: 16 chunks x 24576 B
    const char* wslab = (const char*)g_w + (size_t)(bq * 2 + ot) * 16 * 24576;
    const int ipg = tid >> 5;   // x-fill: i-pair (0..7)
    const int lng = tid & 31;   // x-fill: lane -> l

    float xr[5][2];

    auto fillA = [&](int ic, int s) {
        const char* slab = wslab + (size_t)ic * 24576;
        #pragma unroll
        for (int j = 0; j < 6; j++) {
            int u = tid + 256 * j;              // 0..1535
            int tile = u >> 8, rem = u & 255;   // row=rem>>1, seg=rem&1
            cp_async16(sb + OFF_A + s * AST + tile * ATILE + (rem >> 1) * 48 + (rem & 1) * 16,
                       slab + (size_t)u * 16);
        }
    };
    auto ldgX = [&](int ic) {
        #pragma unroll
        for (int r = 0; r < 5; r++) {
            int lp = lng + 32 * r;
            int gl = l0 - 1 + lp;
            bool ok = (lp < 130) && (gl >= 0) && (gl < LDIMC);
            size_t gi = (size_t)(ic * IC + 2 * ipg) * LDIMC + gl;
            xr[r][0] = ok ? __ldg(xb + gi) : 0.f;
            xr[r][1] = ok ? __ldg(xb + gi + LDIMC) : 0.f;
        }
    };
    auto stsX = [&](int s) {
        char* xh = smem + OFF_X + s * XST;
        char* xl = xh + 6240;
        #pragma unroll
        for (int r = 0; r < 5; r++) {
            int lp = lng + 32 * r;
            if (lp < 130) {
                float v0 = xr[r][0], v1 = xr[r][1];
                uint32_t hp = pack_hi(v0, v1);
                float h0 = __uint_as_float(hp << 16);
                float h1 = __uint_as_float(hp & 0xFFFF0000u);
                uint32_t lo = pack_hi(v0 - h0, v1 - h1);
                *(uint32_t*)(xh + lp * 48 + ipg * 4) = hp;
                *(uint32_t*)(xl + lp * 48 + ipg * 4) = lo;
            }
        }
    };

    // ---- prologue: stage 0 ----
    fillA(0, 0); CP_COMMIT();
    ldgX(0);
    CP_WAIT0();
    stsX(0);
    __syncthreads();

    for (int ic = 0; ic < NCH; ic++) {
        const int s = ic & 1;
        if (ic + 1 < NCH) {
            fillA(ic + 1, s ^ 1); CP_COMMIT();
            ldgX(ic + 1);
        }

        const uint32_t aA  = sb + OFF_A + s * AST;
        const uint32_t aXH = sb + OFF_X + s * XST;
        const uint32_t aXL = aXH + 6240;
        #pragma unroll
        for (int tap = 0; tap < 3; tap++) {
            uint32_t bh[4][2], bl[4][2];
            #pragma unroll
            for (int np = 0; np < 2; np++) {
                uint32_t rr[4];
                uint32_t rowb = tap + wn * 32 + np * 16 + bro;
                ldsm4(rr, aXH + rowb * 48 + bko);
                bh[np * 2][0] = rr[0]; bh[np * 2][1] = rr[1];
                bh[np * 2 + 1][0] = rr[2]; bh[np * 2 + 1][1] = rr[3];
                ldsm4(rr, aXL + rowb * 48 + bko);
                bl[np * 2][0] = rr[0]; bl[np * 2][1] = rr[1];
                bl[np * 2 + 1][0] = rr[2]; bl[np * 2 + 1][1] = rr[3];
            }
            #pragma unroll
            for (int mf = 0; mf < 4; mf++) {
                uint32_t ah[4], al[4];
                uint32_t rowa = wm * 64 + mf * 16 + aro;
                ldsm4(ah, aA + (tap * 2 + 0) * ATILE + rowa * 48 + ako);
                ldsm4(al, aA + (tap * 2 + 1) * ATILE + rowa * 48 + ako);
                #pragma unroll
                for (int nf = 0; nf < 4; nf++) mma16816(acc[mf][nf], ah, bh[nf]);
                #pragma unroll
                for (int nf = 0; nf < 4; nf++) mma16816(acc[mf][nf], al, bh[nf]);
                #pragma unroll
                for (int nf = 0; nf < 4; nf++) mma16816(acc[mf][nf], ah, bl[nf]);
            }
        }

        if (ic + 1 < NCH) {
            CP_WAIT0();
            stsX(s ^ 1);
        }
        __syncthreads();
    }

    // ---- epilogue: fragments + bias -> global ----
    const float* bagg = (const float*)smem;
    #pragma unroll
    for (int mf = 0; mf < 4; mf++) {
        int rl = wm * 64 + mf * 16 + (lane >> 2);
        float b0 = bagg[rl], b1 = bagg[rl + 8];
        size_t ro0 = ((size_t)(bq * COUTC + o0 + rl)) * LDIMC;
        size_t ro1 = ro0 + 8 * LDIMC;
        #pragma unroll
        for (int nf = 0; nf < 4; nf++) {
            int c = l0 + wn * 32 + nf * 8 + 2 * (lane & 3);
            float2 v0 = make_float2(acc[mf][nf][0] + b0, acc[mf][nf][1] + b0);
            float2 v1 = make_float2(acc[mf][nf][2] + b1, acc[mf][nf][3] + b1);
            *(float2*)(out + ro0 + c) = v0;
            *(float2*)(out + ro1 + c) = v1;
        }
    }
}

// ---------------------------------------------------------------------------
extern "C" void kernel_launch(void* const* d_in, const int* in_sizes, int n_in,
                              void* d_out, int out_size) {
    const float* x      = (const float*)d_in[0];  // (64,256,1024,1)
    const float* cond   = (const float*)d_in[1];  // (64,256)
    const float* w1     = (const float*)d_in[2];  // (64,256)
    const float* w2     = (const float*)d_in[3];  // (4,64)
    const float* weight = (const float*)d_in[4];  // (4,256,256,3,3)
    const float* bias   = (const float*)d_in[5];  // (4,256)
    float* out = (float*)d_out;                   // (64,256,1024,1)

    cudaFuncSetAttribute(gemm_kernel, cudaFuncAttributeMaxDynamicSharedMemorySize,
                         SMEMSZ);

    att_kernel<<<NB, 256>>>(cond, w1, w2);
    agg_kernel<<<384, 256>>>(weight);
    dim3 grid(16, NB);
    gemm_kernel<<<grid, 256, SMEMSZ>>>(x, bias, out);
}